// round 16
// baseline (speedup 1.0000x reference)
#include <cuda_runtime.h>
#include <math.h>

#define N_EL 4096
#define N_NB 32
#define F_IN 5
#define EDGE_FEAT 32
#define FEAT 256
#define CUTOFF_F 3.0f

// Fused kernel, role-interleaved 1D grid: bid&1 = role, bid>>1 = n.
// Identical to confirmed-best R14 except stores use .wt (write-through)
// instead of .cs (evict-first streaming).
__global__ __launch_bounds__(256)
void fused_kernel(
    const float* __restrict__ r,        // [N,3]
    const float* __restrict__ r_nb,     // [N,K,3]
    const float* __restrict__ fkern,    // [N,5,32]
    const float* __restrict__ fbias,    // [N,32]
    const float* __restrict__ Wg,       // [32,256]
    const float* __restrict__ ekern,    // [N,5,256]
    const float* __restrict__ ebias,    // [N,256]
    const int*   __restrict__ s,        // [N]
    const int*   __restrict__ s_nb,     // [N,K]
    float*       __restrict__ out)      // [2, N, K, 256]
{
    const int bid  = blockIdx.x;
    const int role = bid & 1;           // block-uniform
    const int n    = bid >> 1;
    const int tid  = threadIdx.x;

    __shared__ __align__(16) float sh_feats[N_NB][8];        // premult feats + bias-scale
    __shared__ __align__(16) float sh_fk[F_IN][EDGE_FEAT];   // 5x32  (role 0)
    __shared__ __align__(16) float sh_fb[EDGE_FEAT];         // 32    (role 0)
    __shared__ __align__(16) float sh_fkW[6][FEAT];          // rows 0-4 Fk@W, row 5 fb@W

    // ---- feats + envelope (threads 0..31) ----
    if (tid < N_NB) {
        const int k = tid;
        float rx = r[n * 3 + 0], ry = r[n * 3 + 1], rz = r[n * 3 + 2];
        const float* rn = &r_nb[((size_t)n * N_NB + k) * 3];
        float dx = rn[0] - rx, dy = rn[1] - ry, dz = rn[2] - rz;
        float dist = sqrtf(dx * dx + dy * dy + dz * dz);
        float env = 0.0f;
        if (dist < CUTOFF_F) {
            float x = dist * (1.0f / CUTOFF_F);
            if (x > 1.0f) x = 1.0f;
            env = 0.5f * (cospif(x) + 1.0f);
        }
        float same = (s[n] == s_nb[(size_t)n * N_NB + k]) ? 1.0f : 0.0f;
        // role 0: premultiply env into feats, bias-scale = env
        // role 1: raw feats, bias-scale = 1
        float m  = (role == 0) ? env : 1.0f;
        float4* fp = (float4*)&sh_feats[k][0];
        fp[0] = make_float4(dx * m, dy * m, dz * m, dist * m);
        fp[1] = make_float4(same * m, m, 0.0f, 0.0f);
    }

    // ---- role 0: stage per-n filter params (threads 64..255) ----
    if (role == 0 && tid >= 64) {
        const int i = tid - 64;                    // 0..191
        if (i < F_IN * EDGE_FEAT) {
            sh_fk[i / EDGE_FEAT][i % EDGE_FEAT] = fkern[(size_t)n * F_IN * EDGE_FEAT + i];
        } else {
            sh_fb[i - F_IN * EDGE_FEAT] = fbias[(size_t)n * EDGE_FEAT + (i - F_IN * EDGE_FEAT)];
        }
    }
    __syncthreads();

    const int dg = tid & 63;      // 0..63 varies within warp -> coalesced stores
    const int kq = tid >> 6;      // 0..3  uniform within warp -> broadcast feat loads
    const int d0 = dg * 4;

    float4 c0, c1, c2, c3, c4, cb;

    if (role == 0) {
        // ---- FkW = Fk @ Wg, fbW = fb @ Wg; one d column per thread ----
        const int d = tid;
        float a0 = 0.f, a1 = 0.f, a2 = 0.f, a3 = 0.f, a4 = 0.f, ab = 0.f;
#pragma unroll
        for (int e4 = 0; e4 < EDGE_FEAT; e4 += 4) {
            float4 vb = *(const float4*)&sh_fb[e4];
            float4 v0 = *(const float4*)&sh_fk[0][e4];
            float4 v1 = *(const float4*)&sh_fk[1][e4];
            float4 v2 = *(const float4*)&sh_fk[2][e4];
            float4 v3 = *(const float4*)&sh_fk[3][e4];
            float4 v4 = *(const float4*)&sh_fk[4][e4];
            float w0 = Wg[(e4 + 0) * FEAT + d];
            float w1 = Wg[(e4 + 1) * FEAT + d];
            float w2 = Wg[(e4 + 2) * FEAT + d];
            float w3 = Wg[(e4 + 3) * FEAT + d];
            ab += vb.x * w0 + vb.y * w1 + vb.z * w2 + vb.w * w3;
            a0 += v0.x * w0 + v0.y * w1 + v0.z * w2 + v0.w * w3;
            a1 += v1.x * w0 + v1.y * w1 + v1.z * w2 + v1.w * w3;
            a2 += v2.x * w0 + v2.y * w1 + v2.z * w2 + v2.w * w3;
            a3 += v3.x * w0 + v3.y * w1 + v3.z * w2 + v3.w * w3;
            a4 += v4.x * w0 + v4.y * w1 + v4.z * w2 + v4.w * w3;
        }
        sh_fkW[0][d] = a0; sh_fkW[1][d] = a1; sh_fkW[2][d] = a2;
        sh_fkW[3][d] = a3; sh_fkW[4][d] = a4; sh_fkW[5][d] = ab;
        __syncthreads();

        c0 = *(const float4*)&sh_fkW[0][d0];
        c1 = *(const float4*)&sh_fkW[1][d0];
        c2 = *(const float4*)&sh_fkW[2][d0];
        c3 = *(const float4*)&sh_fkW[3][d0];
        c4 = *(const float4*)&sh_fkW[4][d0];
        cb = *(const float4*)&sh_fkW[5][d0];
    } else {
        const float* base = &ekern[(size_t)n * F_IN * FEAT + d0];
        c0 = *(const float4*)&base[0 * FEAT];
        c1 = *(const float4*)&base[1 * FEAT];
        c2 = *(const float4*)&base[2 * FEAT];
        c3 = *(const float4*)&base[3 * FEAT];
        c4 = *(const float4*)&base[4 * FEAT];
        cb = *(const float4*)&ebias[(size_t)n * FEAT + d0];
    }

    // ---- branch-free main loop: 8 k's per thread, float4 .wt stores ----
    const size_t EOFF  = (size_t)N_EL * N_NB * FEAT;
    const size_t obase = (size_t)role * EOFF + (size_t)n * N_NB * FEAT
                       + (size_t)kq * 8 * FEAT + d0;

#pragma unroll
    for (int kk = 0; kk < 8; kk++) {
        const int k = kq * 8 + kk;
        float4 fa = *(const float4*)&sh_feats[k][0];   // f0..f3 (broadcast LDS)
        float4 fe = *(const float4*)&sh_feats[k][4];   // f4, bs

        const float f0 = fa.x, f1 = fa.y, f2 = fa.z, f3 = fa.w;
        const float f4 = fe.x, bs = fe.y;

        float4 o;
        o.x = bs * cb.x + f0 * c0.x + f1 * c1.x + f2 * c2.x + f3 * c3.x + f4 * c4.x;
        o.y = bs * cb.y + f0 * c0.y + f1 * c1.y + f2 * c2.y + f3 * c3.y + f4 * c4.y;
        o.z = bs * cb.z + f0 * c0.z + f1 * c1.z + f2 * c2.z + f3 * c3.z + f4 * c4.z;
        o.w = bs * cb.w + f0 * c0.w + f1 * c1.w + f2 * c2.w + f3 * c3.w + f4 * c4.w;

        __stwt((float4*)&out[obase + (size_t)kk * FEAT], o);   // write-through
    }
}

extern "C" void kernel_launch(void* const* d_in, const int* in_sizes, int n_in,
                              void* d_out, int out_size) {
    const float* r     = (const float*)d_in[0];
    const float* r_nb  = (const float*)d_in[1];
    const float* fkern = (const float*)d_in[2];
    const float* fbias = (const float*)d_in[3];
    const float* Wg    = (const float*)d_in[4];
    const float* ekern = (const float*)d_in[5];
    const float* ebias = (const float*)d_in[6];
    const int*   s     = (const int*)d_in[7];
    const int*   s_nb  = (const int*)d_in[8];
    float* out = (float*)d_out;

    fused_kernel<<<N_EL * 2, 256>>>(r, r_nb, fkern, fbias, Wg, ekern, ebias, s, s_nb, out);
}

// round 17
// speedup vs baseline: 1.1627x; 1.1627x over previous
#include <cuda_runtime.h>
#include <math.h>

#define N_EL 4096
#define N_NB 32
#define F_IN 5
#define EDGE_FEAT 32
#define FEAT 256
#define CUTOFF_F 3.0f

// FINAL (confirmed best, R14): fused kernel, role-interleaved 1D grid.
// bid&1 = role (0 -> Gamma, 1 -> edge_features), bid>>1 = n.
// Adjacent blocks alternate roles so every wave mixes FkW-compute blocks with
// pure-stream blocks. 256 threads, 48 regs, 5 blocks/SM, __stcs stores.
// Key algebraic rewrite: Gamma = env*(feats@Fk + fb)@W = env*(feats@(Fk@W) + fb@W),
// with FkW (5x256) computed once per block in smem -> 3x FLOP reduction.
__global__ __launch_bounds__(256)
void fused_kernel(
    const float* __restrict__ r,        // [N,3]
    const float* __restrict__ r_nb,     // [N,K,3]
    const float* __restrict__ fkern,    // [N,5,32]
    const float* __restrict__ fbias,    // [N,32]
    const float* __restrict__ Wg,       // [32,256]
    const float* __restrict__ ekern,    // [N,5,256]
    const float* __restrict__ ebias,    // [N,256]
    const int*   __restrict__ s,        // [N]
    const int*   __restrict__ s_nb,     // [N,K]
    float*       __restrict__ out)      // [2, N, K, 256]
{
    const int bid  = blockIdx.x;
    const int role = bid & 1;           // block-uniform
    const int n    = bid >> 1;
    const int tid  = threadIdx.x;

    __shared__ __align__(16) float sh_feats[N_NB][8];        // premult feats + bias-scale
    __shared__ __align__(16) float sh_fk[F_IN][EDGE_FEAT];   // 5x32  (role 0)
    __shared__ __align__(16) float sh_fb[EDGE_FEAT];         // 32    (role 0)
    __shared__ __align__(16) float sh_fkW[6][FEAT];          // rows 0-4 Fk@W, row 5 fb@W

    // ---- feats + envelope (threads 0..31) ----
    if (tid < N_NB) {
        const int k = tid;
        float rx = r[n * 3 + 0], ry = r[n * 3 + 1], rz = r[n * 3 + 2];
        const float* rn = &r_nb[((size_t)n * N_NB + k) * 3];
        float dx = rn[0] - rx, dy = rn[1] - ry, dz = rn[2] - rz;
        float dist = sqrtf(dx * dx + dy * dy + dz * dz);
        float env = 0.0f;
        if (dist < CUTOFF_F) {
            float x = dist * (1.0f / CUTOFF_F);
            if (x > 1.0f) x = 1.0f;
            env = 0.5f * (cospif(x) + 1.0f);
        }
        float same = (s[n] == s_nb[(size_t)n * N_NB + k]) ? 1.0f : 0.0f;
        // role 0: premultiply env into feats, bias-scale = env
        // role 1: raw feats, bias-scale = 1
        float m  = (role == 0) ? env : 1.0f;
        float4* fp = (float4*)&sh_feats[k][0];
        fp[0] = make_float4(dx * m, dy * m, dz * m, dist * m);
        fp[1] = make_float4(same * m, m, 0.0f, 0.0f);
    }

    // ---- role 0: stage per-n filter params (threads 64..255) ----
    if (role == 0 && tid >= 64) {
        const int i = tid - 64;                    // 0..191
        if (i < F_IN * EDGE_FEAT) {
            sh_fk[i / EDGE_FEAT][i % EDGE_FEAT] = fkern[(size_t)n * F_IN * EDGE_FEAT + i];
        } else {
            sh_fb[i - F_IN * EDGE_FEAT] = fbias[(size_t)n * EDGE_FEAT + (i - F_IN * EDGE_FEAT)];
        }
    }
    __syncthreads();

    const int dg = tid & 63;      // 0..63 varies within warp -> coalesced stores
    const int kq = tid >> 6;      // 0..3  uniform within warp -> broadcast feat loads
    const int d0 = dg * 4;

    float4 c0, c1, c2, c3, c4, cb;

    if (role == 0) {
        // ---- FkW = Fk @ Wg, fbW = fb @ Wg; one d column per thread ----
        const int d = tid;
        float a0 = 0.f, a1 = 0.f, a2 = 0.f, a3 = 0.f, a4 = 0.f, ab = 0.f;
#pragma unroll
        for (int e4 = 0; e4 < EDGE_FEAT; e4 += 4) {
            float4 vb = *(const float4*)&sh_fb[e4];
            float4 v0 = *(const float4*)&sh_fk[0][e4];
            float4 v1 = *(const float4*)&sh_fk[1][e4];
            float4 v2 = *(const float4*)&sh_fk[2][e4];
            float4 v3 = *(const float4*)&sh_fk[3][e4];
            float4 v4 = *(const float4*)&sh_fk[4][e4];
            float w0 = Wg[(e4 + 0) * FEAT + d];
            float w1 = Wg[(e4 + 1) * FEAT + d];
            float w2 = Wg[(e4 + 2) * FEAT + d];
            float w3 = Wg[(e4 + 3) * FEAT + d];
            ab += vb.x * w0 + vb.y * w1 + vb.z * w2 + vb.w * w3;
            a0 += v0.x * w0 + v0.y * w1 + v0.z * w2 + v0.w * w3;
            a1 += v1.x * w0 + v1.y * w1 + v1.z * w2 + v1.w * w3;
            a2 += v2.x * w0 + v2.y * w1 + v2.z * w2 + v2.w * w3;
            a3 += v3.x * w0 + v3.y * w1 + v3.z * w2 + v3.w * w3;
            a4 += v4.x * w0 + v4.y * w1 + v4.z * w2 + v4.w * w3;
        }
        sh_fkW[0][d] = a0; sh_fkW[1][d] = a1; sh_fkW[2][d] = a2;
        sh_fkW[3][d] = a3; sh_fkW[4][d] = a4; sh_fkW[5][d] = ab;
        __syncthreads();

        c0 = *(const float4*)&sh_fkW[0][d0];
        c1 = *(const float4*)&sh_fkW[1][d0];
        c2 = *(const float4*)&sh_fkW[2][d0];
        c3 = *(const float4*)&sh_fkW[3][d0];
        c4 = *(const float4*)&sh_fkW[4][d0];
        cb = *(const float4*)&sh_fkW[5][d0];
    } else {
        const float* base = &ekern[(size_t)n * F_IN * FEAT + d0];
        c0 = *(const float4*)&base[0 * FEAT];
        c1 = *(const float4*)&base[1 * FEAT];
        c2 = *(const float4*)&base[2 * FEAT];
        c3 = *(const float4*)&base[3 * FEAT];
        c4 = *(const float4*)&base[4 * FEAT];
        cb = *(const float4*)&ebias[(size_t)n * FEAT + d0];
    }

    // ---- branch-free main loop: 8 k's per thread, float4 .cs stores ----
    const size_t EOFF  = (size_t)N_EL * N_NB * FEAT;
    const size_t obase = (size_t)role * EOFF + (size_t)n * N_NB * FEAT
                       + (size_t)kq * 8 * FEAT + d0;

#pragma unroll
    for (int kk = 0; kk < 8; kk++) {
        const int k = kq * 8 + kk;
        float4 fa = *(const float4*)&sh_feats[k][0];   // f0..f3 (broadcast LDS)
        float4 fe = *(const float4*)&sh_feats[k][4];   // f4, bs

        const float f0 = fa.x, f1 = fa.y, f2 = fa.z, f3 = fa.w;
        const float f4 = fe.x, bs = fe.y;

        float4 o;
        o.x = bs * cb.x + f0 * c0.x + f1 * c1.x + f2 * c2.x + f3 * c3.x + f4 * c4.x;
        o.y = bs * cb.y + f0 * c0.y + f1 * c1.y + f2 * c2.y + f3 * c3.y + f4 * c4.y;
        o.z = bs * cb.z + f0 * c0.z + f1 * c1.z + f2 * c2.z + f3 * c3.z + f4 * c4.z;
        o.w = bs * cb.w + f0 * c0.w + f1 * c1.w + f2 * c2.w + f3 * c3.w + f4 * c4.w;

        __stcs((float4*)&out[obase + (size_t)kk * FEAT], o);
    }
}

extern "C" void kernel_launch(void* const* d_in, const int* in_sizes, int n_in,
                              void* d_out, int out_size) {
    const float* r     = (const float*)d_in[0];
    const float* r_nb  = (const float*)d_in[1];
    const float* fkern = (const float*)d_in[2];
    const float* fbias = (const float*)d_in[3];
    const float* Wg    = (const float*)d_in[4];
    const float* ekern = (const float*)d_in[5];
    const float* ebias = (const float*)d_in[6];
    const int*   s     = (const int*)d_in[7];
    const int*   s_nb  = (const int*)d_in[8];
    float* out = (float*)d_out;

    fused_kernel<<<N_EL * 2, 256>>>(r, r_nb, fkern, fbias, Wg, ekern, ebias, s, s_nb, out);
}